// round 6
// baseline (speedup 1.0000x reference)
#include <cuda_runtime.h>
#include <cuda_bf16.h>

// NeuralODE R6: R5 math (f32x2 across hidden dim, 4-way shared reciprocal,
// zero-MOV smem operand layout) + grid reshaped to 2048 CTAs of 64 threads
// (16 CTA/SM reg-exact -> ~27.7 warps/SM) + paired float4 output stores.

#define NB    131072
#define NSEQ  150
#define ND    2
#define NH    64
#define NPRED 150
#define NSTEPS (NPRED - 1)

typedef unsigned long long u64;

__device__ __forceinline__ u64 pk(float a, float b) {
    u64 r; asm("mov.b64 %0, {%1, %2};" : "=l"(r) : "f"(a), "f"(b)); return r;
}
__device__ __forceinline__ float2 upk(u64 v) {
    float2 r; asm("mov.b64 {%0, %1}, %2;" : "=f"(r.x), "=f"(r.y) : "l"(v)); return r;
}
__device__ __forceinline__ u64 fma2(u64 a, u64 b, u64 c) {
    u64 d; asm("fma.rn.f32x2 %0, %1, %2, %3;" : "=l"(d) : "l"(a), "l"(b), "l"(c)); return d;
}
__device__ __forceinline__ u64 add2(u64 a, u64 b) {
    u64 d; asm("add.rn.f32x2 %0, %1, %2;" : "=l"(d) : "l"(a), "l"(b)); return d;
}
__device__ __forceinline__ float ex2f(float p) {
    float t; asm("ex2.approx.f32 %0, %1;" : "=f"(t) : "f"(p)); return t;
}
__device__ __forceinline__ float rcpf(float p) {
    float t; asm("rcp.approx.f32 %0, %1;" : "=f"(t) : "f"(p)); return t;
}

// Shared layout per jp (hidden pair {2jp, 2jp+1}):
//   sW[jp] = ulonglong2 { {s*wx_j, s*wx_j1}, {s*wy_j, s*wy_j1} }
//   sV[jp] = ulonglong2 { {vx_j, vx_j1},   {vy_j, vy_j1} }
//   sB[jp] = u64 {s*b_j, s*b_j1},  s = 2*log2(e)
// tanh folded into epilogue: o = c - 2*sum(r*v), r = 1/(2^p+1), p clamped <= 31.
__device__ __forceinline__ void feval(float y0, float y1,
                                      const ulonglong2* __restrict__ sW,
                                      const u64* __restrict__ sB,
                                      const ulonglong2* __restrict__ sV,
                                      float c0, float c1,
                                      float& o0, float& o1) {
    const u64 y0p = pk(y0, y0);
    const u64 y1p = pk(y1, y1);
    u64 a0a = 0ull, a1a = 0ull;
    u64 a0b = 0ull, a1b = 0ull;
#pragma unroll 4
    for (int jp = 0; jp < NH / 2; jp += 2) {
        ulonglong2 W0 = sW[jp];
        ulonglong2 W1 = sW[jp + 1];
        u64 B0 = sB[jp];
        u64 B1 = sB[jp + 1];
        u64 pA = fma2(y0p, W0.x, fma2(y1p, W0.y, B0));
        u64 pB = fma2(y0p, W1.x, fma2(y1p, W1.y, B1));
        float2 a = upk(pA), b = upk(pB);

        float t0 = ex2f(fminf(a.x, 31.0f));
        float t1 = ex2f(fminf(a.y, 31.0f));
        float t2 = ex2f(fminf(b.x, 31.0f));
        float t3 = ex2f(fminf(b.y, 31.0f));
        float u0 = t0 + 1.0f, u1 = t1 + 1.0f;
        float u2 = t2 + 1.0f, u3 = t3 + 1.0f;

        // 4-way shared reciprocal: one MUFU rcp serves 4 sigmoids.
        // p <= 31 -> u <= 2^31+1, 4-product <= ~2^124 (finite).
        float m01 = u0 * u1;
        float m23 = u2 * u3;
        float rc  = rcpf(m01 * m23);
        float rA  = rc * m23;                 // = 1/m01
        float rB  = rc * m01;                 // = 1/m23
        u64 r01 = pk(rA * u1, rA * u0);       // {1/u0, 1/u1}
        u64 r23 = pk(rB * u3, rB * u2);       // {1/u2, 1/u3}

        ulonglong2 V0 = sV[jp];
        ulonglong2 V1 = sV[jp + 1];
        a0a = fma2(r01, V0.x, a0a);
        a1a = fma2(r01, V0.y, a1a);
        a0b = fma2(r23, V1.x, a0b);
        a1b = fma2(r23, V1.y, a1b);
    }
    float2 s0 = upk(add2(a0a, a0b));
    float2 s1 = upk(add2(a1a, a1b));
    o0 = fmaf(-2.0f, s0.x + s0.y, c0);
    o1 = fmaf(-2.0f, s1.x + s1.y, c1);
}

// One RK-3/8 step: (y0,y1) -> (y0',y1')
__device__ __forceinline__ void rk_step(float& y0, float& y1,
                                        const ulonglong2* __restrict__ sW,
                                        const u64* __restrict__ sB,
                                        const ulonglong2* __restrict__ sV,
                                        float c0, float c1) {
    const float dt   = (float)(150.0 / 149.0);
    const float dt3  = dt * (1.0f / 3.0f);
    const float dt8  = dt * 0.125f;
    const float thrd = 1.0f / 3.0f;

    float k1x, k1y, k2x, k2y, k3x, k3y, k4x, k4y;
    feval(y0, y1, sW, sB, sV, c0, c1, k1x, k1y);
    feval(fmaf(dt3, k1x, y0), fmaf(dt3, k1y, y1), sW, sB, sV, c0, c1, k2x, k2y);
    feval(fmaf(dt, fmaf(-thrd, k1x, k2x), y0),
          fmaf(dt, fmaf(-thrd, k1y, k2y), y1), sW, sB, sV, c0, c1, k3x, k3y);
    feval(fmaf(dt, (k1x - k2x) + k3x, y0),
          fmaf(dt, (k1y - k2y) + k3y, y1), sW, sB, sV, c0, c1, k4x, k4y);

    y0 = fmaf(dt8, fmaf(3.0f, k2x + k3x, k1x + k4x), y0);
    y1 = fmaf(dt8, fmaf(3.0f, k2y + k3y, k1y + k4y), y1);
}

__global__ void __launch_bounds__(64, 16)
neural_ode_kernel(const float* __restrict__ x,
                  const float* __restrict__ W1,
                  const float* __restrict__ b1,
                  const float* __restrict__ W2,
                  const float* __restrict__ b2,
                  float* __restrict__ out) {
    __shared__ alignas(16) float4 sWf[NH / 2];
    __shared__ alignas(16) float4 sVf[NH / 2];
    __shared__ alignas(8)  float2 sBf[NH / 2];
    __shared__ float sc[2];

    const int tid = threadIdx.x;
    if (tid < NH / 2) {
        const float s = 2.8853900817779268f;  // 2*log2(e)
        int j = 2 * tid;
        sWf[tid] = make_float4(s * W1[j], s * W1[j + 1],
                               s * W1[NH + j], s * W1[NH + j + 1]);
        sBf[tid] = make_float2(s * b1[j], s * b1[j + 1]);
        sVf[tid] = make_float4(W2[2 * j], W2[2 * (j + 1)],
                               W2[2 * j + 1], W2[2 * (j + 1) + 1]);
    }
    if (tid < 2) {
        float c = b2[tid];
        for (int j = 0; j < NH; j++) c += W2[2 * j + tid];
        sc[tid] = c;
    }
    __syncthreads();

    const ulonglong2* sW = reinterpret_cast<const ulonglong2*>(sWf);
    const ulonglong2* sV = reinterpret_cast<const ulonglong2*>(sVf);
    const u64*        sB = reinterpret_cast<const u64*>(sBf);

    const float c0 = sc[0];
    const float c1 = sc[1];

    const long b = (long)blockIdx.x * blockDim.x + tid;

    const float2 yin = *(const float2*)(x + b * (long)(NSEQ * ND) + (NSEQ - 1) * ND);
    float y0 = yin.x;
    float y1 = yin.y;

    // Output written as float4 pairs: slot k = {y(2k).x, y(2k).y, y(2k+1).x, y(2k+1).y}
    float4* ob4 = (float4*)(out + b * (long)(NPRED * ND));

#pragma unroll 1
    for (int k = 0; k < 74; k++) {
        float p0 = y0, p1 = y1;
        rk_step(y0, y1, sW, sB, sV, c0, c1);           // y(2k+1)
        ob4[k] = make_float4(p0, p1, y0, y1);
        rk_step(y0, y1, sW, sB, sV, c0, c1);           // y(2k+2)
    }
    // Last pair: y(148) already in regs; compute y(149)
    {
        float p0 = y0, p1 = y1;
        rk_step(y0, y1, sW, sB, sV, c0, c1);           // y(149)
        ob4[74] = make_float4(p0, p1, y0, y1);
    }
}

extern "C" void kernel_launch(void* const* d_in, const int* in_sizes, int n_in,
                              void* d_out, int out_size) {
    const float* x  = (const float*)d_in[0];
    const float* W1 = (const float*)d_in[1];
    const float* b1 = (const float*)d_in[2];
    const float* W2 = (const float*)d_in[3];
    const float* b2 = (const float*)d_in[4];
    float* out = (float*)d_out;

    const int block = 64;
    const int grid  = NB / block;  // 2048 CTAs, 4096 warps
    neural_ode_kernel<<<grid, block>>>(x, W1, b1, W2, b2, out);
}